// round 15
// baseline (speedup 1.0000x reference)
#include <cuda_runtime.h>
#include <cuda_fp16.h>
#include <math.h>
#include <cstdint>

#define TOK   8192
#define DIM   384
#define NSEQ  2048
#define NHEAD 6
#define HD    64
#define KNN   8
#define QS    1920   // row stride of merged [q|k|v|P|R2] buffer

// ---------------- static scratch (no allocations allowed) -------------------
// fp32 floats: attn@0, knn@3145728, x1@6291456
__device__ __align__(128) float g_buf[9437184];
__device__ int g_idx64;

__device__ __align__(128) __half g_nx[TOK * DIM];
__device__ __align__(128) __half g_qkvpr[TOK * QS];   // [q|k|v|P|R2]
__device__ __align__(128) __half g_ap[TOK * DIM];
__device__ __align__(128) __half g_gi[TOK * 2 * DIM];
__device__ __align__(128) __half g_g1[TOK * DIM];
__device__ __align__(128) __half g_nx2[TOK * DIM];
__device__ __align__(128) __half g_hb[TOK * 4 * DIM];
__device__ __align__(128) __half g_wh[2506752];

#define W_QKV  0          // 1152x384
#define W_KNN1 442368     //  384x384
#define W_KNN2 589824     //  384x384
#define W_PROJ 737280     //  384x384
#define W_G1   884736     //  384x768
#define W_G2   1179648    //  384x384
#define W_FC1  1327104    // 1536x384
#define W_FC2  1916928    //  384x1536

// ---------------- helpers ----------------------------------------------------
__device__ __forceinline__ uint32_t smem_to_u32(const void* p) {
    uint32_t a;
    asm("{ .reg .u64 t; cvta.to.shared.u64 t, %1; cvt.u32.u64 %0, t; }" : "=r"(a) : "l"(p));
    return a;
}
#define STS128(r0, r1, r2, r3, sa) \
    asm volatile("st.shared.v4.b32 [%0], {%1, %2, %3, %4};" \
                 :: "r"(sa), "r"(r0), "r"(r1), "r"(r2), "r"(r3) : "memory")
#define SWZ128(o) ((o) ^ (((o) >> 3) & 0x70))
#define CP_ASYNC16(dst, src) \
    asm volatile("cp.async.cg.shared.global [%0], [%1], 16;" :: "r"(dst), "l"(src) : "memory")
#define CP_COMMIT() asm volatile("cp.async.commit_group;" ::: "memory")
#define CP_WAIT0()  asm volatile("cp.async.wait_group 0;" ::: "memory")
#define CP_WAIT1()  asm volatile("cp.async.wait_group 1;" ::: "memory")

__device__ __forceinline__ void ldsm4(uint32_t* r, uint32_t addr) {
    asm volatile("ldmatrix.sync.aligned.m8n8.x4.shared.b16 {%0,%1,%2,%3}, [%4];"
                 : "=r"(r[0]), "=r"(r[1]), "=r"(r[2]), "=r"(r[3]) : "r"(addr));
}
__device__ __forceinline__ void ldsm4t(uint32_t* r, uint32_t addr) {
    asm volatile("ldmatrix.sync.aligned.m8n8.x4.trans.shared.b16 {%0,%1,%2,%3}, [%4];"
                 : "=r"(r[0]), "=r"(r[1]), "=r"(r[2]), "=r"(r[3]) : "r"(addr));
}
__device__ __forceinline__ void mma16816(float* d, const uint32_t* a, const uint32_t* b) {
    asm volatile("mma.sync.aligned.m16n8k16.row.col.f32.f16.f16.f32 "
                 "{%0,%1,%2,%3}, {%4,%5,%6,%7}, {%8,%9}, {%0,%1,%2,%3};"
                 : "+f"(d[0]), "+f"(d[1]), "+f"(d[2]), "+f"(d[3])
                 : "r"(a[0]), "r"(a[1]), "r"(a[2]), "r"(a[3]), "r"(b[0]), "r"(b[1]));
}

__device__ __forceinline__ float geluf(float v) {
    return 0.5f * v * (1.0f + erff(v * 0.70710678118654752f));
}
__device__ __forceinline__ unsigned pk2h(float a, float b) {
    __half2 t = __floats2half2_rn(a, b);
    return *reinterpret_cast<unsigned*>(&t);
}

// ---------------- combined weight transpose -> fp16 (single launch) ---------
struct WSegs {
    const float* W[8];
    int dst[8];
    int K[8];
    int N[8];
    int t0[8];
};

__global__ void __launch_bounds__(256) wsplit_all(WSegs s, __half* __restrict__ ohb)
{
    __shared__ float t[32][33];
    int tb = blockIdx.x;
    int si = 0;
    #pragma unroll
    for (int i = 1; i < 8; i++) si = (tb >= s.t0[i]) ? i : si;
    int lt = tb - s.t0[si];
    const float* W = s.W[si];
    __half* oh = ohb + s.dst[si];
    int K = s.K[si], N = s.N[si];
    int ntx = N >> 5;
    int n0 = (lt % ntx) * 32, k0 = (lt / ntx) * 32;
    int tx = threadIdx.x & 31, ty = threadIdx.x >> 5;
    #pragma unroll
    for (int r = 0; r < 4; r++)
        t[ty + r * 8][tx] = W[(size_t)(k0 + ty + r * 8) * N + n0 + tx];
    __syncthreads();
    #pragma unroll
    for (int r = 0; r < 4; r++) {
        int n = n0 + ty + r * 8, k = k0 + tx;
        oh[(size_t)n * K + k] = __float2half_rn(t[tx][ty + r * 8]);
    }
}

// ---------------- LayerNorm -> fp16 ------------------------------------------
__global__ void __launch_bounds__(128) ln_fp16_kernel(const float* __restrict__ x,
    const float* __restrict__ g, const float* __restrict__ b,
    __half* __restrict__ oh)
{
    __shared__ float s1[4], s2[4];
    int row = blockIdx.x, t = threadIdx.x;
    const float* xr = x + (size_t)row * DIM;
    float v0 = xr[t], v1 = xr[t + 128], v2 = xr[t + 256];
    float sum = v0 + v1 + v2;
    float sq  = v0 * v0 + v1 * v1 + v2 * v2;
    #pragma unroll
    for (int o = 16; o > 0; o >>= 1) {
        sum += __shfl_xor_sync(0xffffffffu, sum, o);
        sq  += __shfl_xor_sync(0xffffffffu, sq,  o);
    }
    int w = t >> 5;
    if ((t & 31) == 0) { s1[w] = sum; s2[w] = sq; }
    __syncthreads();
    sum = s1[0] + s1[1] + s1[2] + s1[3];
    sq  = s2[0] + s2[1] + s2[2] + s2[3];
    float mu  = sum * (1.0f / DIM);
    float var = sq * (1.0f / DIM) - mu * mu;
    float rs  = rsqrtf(var + 1e-5f);
    size_t base = (size_t)row * DIM;
    #pragma unroll
    for (int it = 0; it < 3; it++) {
        int c = t + it * 128;
        float vv = (it == 0 ? v0 : it == 1 ? v1 : v2);
        float f = (vv - mu) * rs * g[c] + b[c];
        oh[base + c] = __float2half_rn(f);
    }
}

// ---------------- int32/int64 detection -------------------------------------
__global__ void detect_kernel(const unsigned int* __restrict__ w)
{
    if (threadIdx.x == 0) {
        unsigned int nz = 0;
        for (int i = 0; i < 512; i++) nz |= w[2 * i + 1];
        g_idx64 = (nz == 0) ? 1 : 0;
    }
}

// ---------------- fp16 GEMM 128x128, single-term, cp.async 2-stage ----------
#define GEMM_SMEM 65536
#define STAGE_SZ  32768u

template <int EPI, int OUTP>
__global__ void __launch_bounds__(256) tcgemm(
    const __half* __restrict__ A,
    const __half* __restrict__ B,
    float* __restrict__ C, __half* __restrict__ Ch,
    int N, int K,
    const float* __restrict__ bias, const float* __restrict__ e1,
    const float* __restrict__ e2, const float* __restrict__ e3)
{
    extern __shared__ char smem[];
    uint32_t sb = smem_to_u32(smem);
    int tid = threadIdx.x, warp = tid >> 5, lane = tid & 31;
    int wr = warp >> 2, wc = warp & 3;
    int n0 = blockIdx.x * 128, m0 = blockIdx.y * 128;

    float acc[4][4][4];
    #pragma unroll
    for (int i = 0; i < 4; i++)
        #pragma unroll
        for (int j = 0; j < 4; j++)
            #pragma unroll
            for (int q = 0; q < 4; q++) acc[i][j][q] = 0.f;

    const __half* src2[2] = { A + (size_t)m0 * K, B + (size_t)n0 * K };

    int lrow = tid >> 3, lseg = tid & 7;
    uint32_t lsw[4];
    #pragma unroll
    for (int i = 0; i < 4; i++)
        lsw[i] = SWZ128((uint32_t)((lrow + i * 32) * 128 + lseg * 16));

    int lr = lane & 7, ls = lane >> 3;
    int a_row = wr * 64 + (ls & 1) * 8 + lr;
    int a_kb  = (ls >> 1) * 16;
    int b_row = wc * 32 + (ls >> 1) * 8 + lr;
    int b_kb  = (ls & 1) * 16;

    int nch = K >> 6;

    #pragma unroll
    for (int t = 0; t < 2; t++) {
        const __half* base = src2[t];
        #pragma unroll
        for (int i = 0; i < 4; i++)
            CP_ASYNC16(sb + t * 16384u + lsw[i],
                       base + (size_t)(lrow + i * 32) * K + lseg * 8);
    }
    CP_COMMIT();

    for (int ch = 0; ch < nch; ch++) {
        if (ch + 1 < nch) {
            uint32_t st = ((ch + 1) & 1) * STAGE_SZ;
            int k0 = (ch + 1) << 6;
            #pragma unroll
            for (int t = 0; t < 2; t++) {
                const __half* base = src2[t] + k0;
                #pragma unroll
                for (int i = 0; i < 4; i++)
                    CP_ASYNC16(sb + st + t * 16384u + lsw[i],
                               base + (size_t)(lrow + i * 32) * K + lseg * 8);
            }
            CP_COMMIT();
            CP_WAIT1();
        } else {
            CP_WAIT0();
        }
        __syncthreads();

        uint32_t st = (ch & 1) * STAGE_SZ;
        #pragma unroll
        for (int ks = 0; ks < 4; ks++) {
            uint32_t ah[4][4], bh[4][2];
            #pragma unroll
            for (int mi = 0; mi < 4; mi++) {
                uint32_t off = (uint32_t)((a_row + mi * 16) * 128 + ks * 32 + a_kb);
                ldsm4(ah[mi], sb + st + SWZ128(off));
            }
            #pragma unroll
            for (int np = 0; np < 2; np++) {
                uint32_t off = (uint32_t)((b_row + np * 16) * 128 + ks * 32 + b_kb);
                uint32_t t4[4];
                ldsm4(t4, sb + st + 16384u + SWZ128(off));
                bh[np * 2][0] = t4[0]; bh[np * 2][1] = t4[1];
                bh[np * 2 + 1][0] = t4[2]; bh[np * 2 + 1][1] = t4[3];
            }
            #pragma unroll
            for (int mi = 0; mi < 4; mi++)
                #pragma unroll
                for (int nj = 0; nj < 4; nj++)
                    mma16816(acc[mi][nj], ah[mi], bh[nj]);
        }
        __syncthreads();
    }

    int g = lane >> 2, tg = lane & 3;
    #pragma unroll
    for (int mi = 0; mi < 4; mi++)
        #pragma unroll
        for (int nj = 0; nj < 4; nj++) {
            int col = n0 + wc * 32 + nj * 8 + 2 * tg;
            float bcol0 = 0.f, bcol1 = 0.f;
            if (EPI >= 1) { bcol0 = bias[col]; bcol1 = bias[col + 1]; }
            #pragma unroll
            for (int half = 0; half < 2; half++) {
                size_t row = (size_t)(m0 + wr * 64 + mi * 16 + g + half * 8);
                float v0 = acc[mi][nj][half * 2]     + bcol0;
                float v1 = acc[mi][nj][half * 2 + 1] + bcol1;
                if (EPI == 2) { v0 = geluf(v0); v1 = geluf(v1); }
                if (EPI == 3) {
                    size_t off = row * (size_t)N + (size_t)col;
                    float2 a1 = *(const float2*)(e1 + off);
                    float2 a2 = *(const float2*)(e2 + off);
                    float2 a3 = *(const float2*)(e3 + off);
                    float s0 = 1.0f / (1.0f + expf(-v0));
                    float s1 = 1.0f / (1.0f + expf(-v1));
                    v0 = a1.x + (1.0f - s0) * a2.x + s0 * a3.x;
                    v1 = a1.y + (1.0f - s1) * a2.y + s1 * a3.y;
                }
                if (EPI == 4) {
                    float2 a1 = *(const float2*)(e1 + row * (size_t)N + col);
                    v0 += a1.x; v1 += a1.y;
                }
                if (OUTP == 0) {
                    *(float2*)(C + row * (size_t)N + col) = make_float2(v0, v1);
                } else if (OUTP == 1) {
                    *(unsigned*)(Ch + row * (size_t)N + col) = pk2h(v0, v1);
                } else {
                    *(float2*)(C + row * (size_t)N + col) = make_float2(v0, v1);
                    *(unsigned*)(Ch + row * 768 + col) = pk2h(v0, v1);
                }
            }
        }
}

// ---------------- fp16 GEMM 256x128, warp tile 64x64, cp.async 2-stage ------
#define GEMM256_SMEM 98304
#define STG256 49152u

template <int EPI, int OUTP>
__global__ void __launch_bounds__(256) tcgemm256(
    const __half* __restrict__ A,
    const __half* __restrict__ B,
    float* __restrict__ C, __half* __restrict__ Ch,
    int N, int K,
    const float* __restrict__ bias)
{
    extern __shared__ char smem[];
    uint32_t sb = smem_to_u32(smem);
    int tid = threadIdx.x, warp = tid >> 5, lane = tid & 31;
    int wr = warp >> 1, wc = warp & 1;
    int n0 = blockIdx.x * 128, m0 = blockIdx.y * 256;

    float acc[4][8][4];
    #pragma unroll
    for (int i = 0; i < 4; i++)
        #pragma unroll
        for (int j = 0; j < 8; j++)
            #pragma unroll
            for (int q = 0; q < 4; q++) acc[i][j][q] = 0.f;

    const __half* pA = A + (size_t)m0 * K;
    const __half* pB = B + (size_t)n0 * K;

    int lrow = tid >> 3, lseg = tid & 7;
    uint32_t lsw[8];
    #pragma unroll
    for (int i = 0; i < 8; i++)
        lsw[i] = SWZ128((uint32_t)((lrow + i * 32) * 128 + lseg * 16));

    int lr = lane & 7, ls = lane >> 3;
    int a_row = wr * 64 + (ls & 1) * 8 + lr;
    int a_kb  = (ls >> 1) * 16;
    int b_row = wc * 64 + (ls >> 1) * 8 + lr;
    int b_kb  = (ls & 1) * 16;

    int nch = K >> 6;

    #pragma unroll
    for (int i = 0; i < 8; i++)
        CP_ASYNC16(sb + lsw[i], pA + (size_t)(lrow + i * 32) * K + lseg * 8);
    #pragma unroll
    for (int i = 0; i < 4; i++)
        CP_ASYNC16(sb + 32768u + lsw[i], pB + (size_t)(lrow + i * 32) * K + lseg * 8);
    CP_COMMIT();

    for (int ch = 0; ch < nch; ch++) {
        if (ch + 1 < nch) {
            uint32_t st = ((ch + 1) & 1) * STG256;
            int k0 = (ch + 1) << 6;
            #pragma unroll
            for (int i = 0; i < 8; i++)
                CP_ASYNC16(sb + st + lsw[i], pA + k0 + (size_t)(lrow + i * 32) * K + lseg * 8);
            #pragma unroll
            for (int i = 0; i < 4; i++)
                CP_ASYNC16(sb + st + 32768u + lsw[i], pB + k0 + (size_t)(lrow + i * 32) * K + lseg * 8);
            CP_COMMIT();
            CP_WAIT1();
        } else {
            CP_WAIT0();
        }
        __syncthreads();

        uint32_t st = (ch & 1) * STG256;
        #pragma unroll
        for (int ks = 0; ks < 4; ks++) {
            uint32_t ah[4][4], bh[8][2];
            #pragma unroll
            for (int mi = 0; mi < 4; mi++) {
                uint32_t off = (uint32_t)((a_row + mi * 16) * 128 + ks * 32 + a_kb);
                ldsm4(ah[mi], sb + st + SWZ128(off));
            }
            #pragma unroll
            for (int np = 0; np < 4; np++) {
                uint32_t off = (uint32_t)((b_row + np * 16) * 128 + ks * 32 + b_kb);
                uint32_t t4[4];
                ldsm4(t4, sb + st + 32768u + SWZ128(off));
                bh[np * 2][0] = t4[0]; bh[np * 2][1] = t4[1];
                bh[np * 2 + 1][0] = t4[2]; bh[np * 2 + 1][1] = t4[3];
            }
            #pragma unroll
            for (int mi = 0; mi < 4; mi++)
                #pragma unroll
                for (int nj = 0; nj < 8; nj++)
                    mma16816(acc[mi][nj], ah[mi], bh[nj]);
        }
        __syncthreads();
    }

    int g = lane >> 2, tg = lane & 3;
    #pragma unroll
    for (int mi = 0; mi < 4; mi++)
        #pragma unroll
        for (int nj = 0; nj < 8; nj++) {
            int col = n0 + wc * 64 + nj * 8 + 2 * tg;
            float bcol0 = 0.f, bcol1 = 0.f;
            if (EPI >= 1) { bcol0 = bias[col]; bcol1 = bias[col + 1]; }
            #pragma unroll
            for (int half = 0; half < 2; half++) {
                size_t row = (size_t)(m0 + wr * 64 + mi * 16 + g + half * 8);
                float v0 = acc[mi][nj][half * 2]     + bcol0;
                float v1 = acc[mi][nj][half * 2 + 1] + bcol1;
                if (EPI == 2) { v0 = geluf(v0); v1 = geluf(v1); }
                if (OUTP == 0) {
                    *(float2*)(C + row * (size_t)N + col) = make_float2(v0, v1);
                } else {
                    *(unsigned*)(Ch + row * (size_t)N + col) = pk2h(v0, v1);
                }
            }
        }
}

// ---------------- fp16 flash attention, 2x64-query tiles per block ----------
// smem: K/V 2 stages (32KB) + Q 128 rows (16KB) = 48KB; 128 threads, occ 3.
// grid = (NSEQ/128, NHEAD, B) = 384 blocks -> single wave; K/V traffic halved.
#define ATTN_SMEM 49152

__global__ void __launch_bounds__(128, 3) attn_mma_kernel(
    const __half* __restrict__ qkv,
    __half* __restrict__ oph)
{
    extern __shared__ char smc[];
    uint32_t sb = smem_to_u32(smc);
    int b = blockIdx.z, h = blockIdx.y, qt = blockIdx.x;
    int tid = threadIdx.x, warp = tid >> 5, lane = tid & 31;
    int lr = lane & 7, ls = lane >> 3;
    int g = lane >> 2, tg = lane & 3;

    const int qbase = b * NSEQ + qt * 128;
    const int qcol = h * HD, kcol = DIM + h * HD, vcol = 2 * DIM + h * HD;

    int lrow = tid >> 3, lseg = tid & 7;
    uint32_t lsw[4];
    #pragma unroll
    for (int i = 0; i < 4; i++)
        lsw[i] = SWZ128((uint32_t)((lrow + i * 16) * 128 + lseg * 16));

    // prefetch K/V(kt=0) -> stage 0
    {
        int tokb = b * NSEQ;
        #pragma unroll
        for (int t = 0; t < 2; t++) {
            int colb = (t == 0) ? kcol : vcol;
            #pragma unroll
            for (int i = 0; i < 4; i++)
                CP_ASYNC16(sb + t * 8192u + lsw[i],
                           qkv + (size_t)(tokb + lrow + i * 16) * QS + colb + lseg * 8);
        }
        CP_COMMIT();
    }

    // stage Q: 128 rows at offset 32768 (16KB)
    #pragma unroll
    for (int i = 0; i < 8; i++) {
        int row = lrow + i * 16;
        uint4 v = *reinterpret_cast<const uint4*>(
            qkv + (size_t)(qbase + row) * QS + qcol + lseg * 8);
        STS128(v.x, v.y, v.z, v.w,
               sb + 32768u + SWZ128((uint32_t)(row * 128 + lseg * 16)));
    }

    float O[2][8][4];
    #pragma unroll
    for (int u = 0; u < 2; u++)
        #pragma unroll
        for (int t = 0; t < 8; t++)
            #pragma unroll
            for (int q = 0; q < 4; q++) O[u][t][q] = 0.f;
    float smax[2][2] = {{-1e30f, -1e30f}, {-1e30f, -1e30f}};
    float ssum[2][2] = {{0.f, 0.f}, {0.f, 0.f}};

    const float SC = 0.125f * 1.44269504088896f;

    int qa_row = warp * 16 + (ls & 1) * 8 + lr;   // + u*64
    int qa_kb  = (ls >> 1) * 16;
    int kb_row = (ls >> 1) * 8 + lr;
    int kb_col = (ls & 1) * 16;
    int v_row = lane & 15;
    int v_col = (lane >> 4) * 16;

    __syncthreads();   // Q staged (prefetch0 handled by wait below)

    for (int kt = 0; kt < NSEQ / 64; kt++) {
        if (kt + 1 < NSEQ / 64) {
            uint32_t st = ((kt + 1) & 1) * 16384u;
            int tokb = b * NSEQ + (kt + 1) * 64;
            #pragma unroll
            for (int t = 0; t < 2; t++) {
                int colb = (t == 0) ? kcol : vcol;
                #pragma unroll
                for (int i = 0; i < 4; i++)
                    CP_ASYNC16(sb + st + t * 8192u + lsw[i],
                               qkv + (size_t)(tokb + lrow + i * 16) * QS + colb + lseg * 8);
            }
            CP_COMMIT();
            CP_WAIT1();
        } else {
            CP_WAIT0();
        }
        __syncthreads();

        uint32_t st = (kt & 1) * 16384u;

        #pragma unroll
        for (int u = 0; u < 2; u++) {
            // reload Q fragments for this 64-row tile (keeps regs low)
            uint32_t Qf[4][4];
            #pragma unroll
            for (int ks = 0; ks < 4; ks++) {
                uint32_t off = (uint32_t)((u * 64 + qa_row) * 128 + ks * 32 + qa_kb);
                ldsm4(Qf[ks], sb + 32768u + SWZ128(off));
            }

            float sacc[8][4];
            #pragma unroll
            for (int t = 0; t < 8; t++)
                #pragma unroll
                for (int q = 0; q < 4; q++) sacc[t][q] = 0.f;
            #pragma unroll
            for (int ks = 0; ks < 4; ks++) {
                #pragma unroll
                for (int np = 0; np < 4; np++) {
                    uint32_t off = (uint32_t)((np * 16 + kb_row) * 128 + ks * 32 + kb_col);
                    uint32_t th[4];
                    ldsm4(th, sb + st + SWZ128(off));
                    mma16816(sacc[np * 2],     Qf[ks], th);
                    mma16816(sacc[np * 2 + 1], Qf[ks], th + 2);
                }
            }

            float rmax[2] = {-1e30f, -1e30f};
            #pragma unroll
            for (int t = 0; t < 8; t++) {
                #pragma unroll
                for (int q = 0; q < 4; q++) sacc[t][q] *= SC;
                rmax[0] = fmaxf(rmax[0], fmaxf(sacc[t][0], sacc[t][1]));
                rmax[1] = fmaxf(rmax[1], fmaxf(sacc[t][2], sacc[t][3]));
            }
            #pragma unroll
            for (int o = 1; o <= 2; o <<= 1) {
                rmax[0] = fmaxf(rmax[0], __shfl_xor_sync(0xffffffffu, rmax[0], o));
                rmax[1] = fmaxf(rmax[1], __shfl_xor_sync(0xffffffffu, rmax[1], o));
            }
            float mn0 = fmaxf(smax[u][0], rmax[0]), mn1 = fmaxf(smax[u][1], rmax[1]);
            if (mn0 != smax[u][0] || mn1 != smax[u][1]) {
                float corr0 = exp2f(smax[u][0] - mn0), corr1 = exp2f(smax[u][1] - mn1);
                ssum[u][0] *= corr0;
                ssum[u][1] *= corr1;
                #pragma unroll
                for (int t = 0; t < 8; t++) {
                    O[u][t][0] *= corr0; O[u][t][1] *= corr0;
                    O[u][t][2] *= corr1; O[u][t][3] *= corr1;
                }
                smax[u][0] = mn0; smax[u][1] = mn1;
            }
            float rsum[2] = {0.f, 0.f};
            #pragma unroll
            for (int t = 0; t < 8; t++) {
                sacc[t][0] = exp2f(sacc[t][0] - mn0);
                sacc[t][1] = exp2f(sacc[t][1] - mn0);
                sacc[t][2] = exp2f(sacc[t][2] - mn1);
                sacc[t][3] = exp2f(sacc[t][3] - mn1);
                rsum[0] += sacc[t][0] + sacc[t][1];
                rsum[1] += sacc[t][2] + sacc[t][3];
            }
            #pragma unroll
            for (int o = 1; o <= 2; o <<= 1) {
                rsum[0] += __shfl_xor_sync(0xffffffffu, rsum[0], o);
                rsum[1] += __shfl_xor_sync(0xffffffffu, rsum[1], o);
            }
            ssum[u][0] += rsum[0];
            ssum[u][1] += rsum[1];

            uint32_t ph[4][4];
            #pragma unroll
            for (int j = 0; j < 4; j++) {
                ph[j][0] = pk2h(sacc[2 * j][0],     sacc[2 * j][1]);
                ph[j][1] = pk2h(sacc[2 * j][2],     sacc[2 * j][3]);
                ph[j][2] = pk2h(sacc[2 * j + 1][0], sacc[2 * j + 1][1]);
                ph[j][3] = pk2h(sacc[2 * j + 1][2], sacc[2 * j + 1][3]);
            }

            #pragma unroll
            for (int ks = 0; ks < 4; ks++) {
                #pragma unroll
                for (int np = 0; np < 4; np++) {
                    uint32_t off = (uint32_t)((ks * 16 + v_row) * 128 + np * 32 + v_col);
                    uint32_t vh[4];
                    ldsm4t(vh, sb + st + 8192u + SWZ128(off));
                    mma16816(O[u][np * 2],     ph[ks], vh);
                    mma16816(O[u][np * 2 + 1], ph[ks], vh + 2);
                }
            }
        }
        __syncthreads();
    }

    #pragma unroll
    for (int u = 0; u < 2; u++) {
        float inv0 = 1.0f / ssum[u][0], inv1 = 1.0f / ssum[u][1];
        size_t row0 = (size_t)(qbase + u * 64 + warp * 16 + g);
        #pragma unroll
        for (int t = 0; t < 8; t++) {
            int col = h * HD + t * 8 + tg * 2;
            *(unsigned*)(oph + row0 * DIM + col)       = pk2h(O[u][t][0] * inv0, O[u][t][1] * inv0);
            *(unsigned*)(oph + (row0 + 8) * DIM + col) = pk2h(O[u][t][2] * inv1, O[u][t][3] * inv1);
        }
    }
}

// ---------------- EdgeConv gather (fp16 P/R2 in merged buffer) ---------------
__global__ void __launch_bounds__(384) knn_kernel(const void* __restrict__ idxraw,
    const __half* __restrict__ qkvpr, const float* __restrict__ bknn,
    float* __restrict__ out, __half* __restrict__ gih)
{
    int mtok = blockIdx.x;
    int c = threadIdx.x;
    int b = mtok >> 11;
    int n = mtok & 2047;
    size_t moff = (size_t)mtok * QS + 1152 + c;
    float base = __half2float(qkvpr[moff + 384]) - __half2float(qkvpr[moff]) + bknn[c];
    float best = -3.4e38f;
    int is64 = g_idx64;
    const long long* i64 = (const long long*)idxraw;
    const int* i32 = (const int*)idxraw;
    size_t ib = (size_t)b * KNN * NSEQ + n;
    #pragma unroll
    for (int k = 0; k < KNN; k++) {
        long long id = is64 ? i64[ib + (size_t)k * NSEQ]
                            : (long long)i32[ib + (size_t)k * NSEQ];
        float v = __half2float(qkvpr[(size_t)id * QS + 1152 + c]) + base;
        v = v > 0.f ? v : 0.2f * v;
        best = fmaxf(best, v);
    }
    out[(size_t)mtok * DIM + c] = best;
    gih[(size_t)mtok * 768 + 384 + c] = __float2half_rn(best);
}

// ---------------- launch ----------------------------------------------------
extern "C" void kernel_launch(void* const* d_in, const int* in_sizes, int n_in,
                              void* d_out, int out_size)
{
    const float* x      = (const float*)d_in[0];
    const void*  knnidx = d_in[1];
    const float* ln1_g  = (const float*)d_in[2];
    const float* ln1_b  = (const float*)d_in[3];
    const float* w_qkv  = (const float*)d_in[4];
    const float* w_proj = (const float*)d_in[5];
    const float* b_proj = (const float*)d_in[6];
    const float* w_knn  = (const float*)d_in[7];
    const float* b_knn  = (const float*)d_in[8];
    const float* w_g1   = (const float*)d_in[9];
    const float* b_g1   = (const float*)d_in[10];
    const float* w_g2   = (const float*)d_in[11];
    const float* b_g2   = (const float*)d_in[12];
    const float* ln2_g  = (const float*)d_in[13];
    const float* ln2_b  = (const float*)d_in[14];
    const float* w_fc1  = (const float*)d_in[15];
    const float* b_fc1  = (const float*)d_in[16];
    const float* w_fc2  = (const float*)d_in[17];
    const float* b_fc2  = (const float*)d_in[18];
    float* out = (float*)d_out;

    float* buf = nullptr;
    cudaGetSymbolAddress((void**)&buf, g_buf);
    float* attn = buf + 0;
    float* knn  = buf + 3145728;
    float* x1   = buf + 6291456;

    __half *nx, *qkvpr, *ap, *gi, *g1, *nx2, *hb, *wh;
    cudaGetSymbolAddress((void**)&nx,    g_nx);
    cudaGetSymbolAddress((void**)&qkvpr, g_qkvpr);
    cudaGetSymbolAddress((void**)&ap,    g_ap);
    cudaGetSymbolAddress((void**)&gi,    g_gi);
    cudaGetSymbolAddress((void**)&g1,    g_g1);
    cudaGetSymbolAddress((void**)&nx2,   g_nx2);
    cudaGetSymbolAddress((void**)&hb,    g_hb);
    cudaGetSymbolAddress((void**)&wh,    g_wh);

    cudaFuncSetAttribute(attn_mma_kernel, cudaFuncAttributeMaxDynamicSharedMemorySize, ATTN_SMEM);
    cudaFuncSetAttribute(tcgemm<1,2>, cudaFuncAttributeMaxDynamicSharedMemorySize, GEMM_SMEM);
    cudaFuncSetAttribute(tcgemm<2,1>, cudaFuncAttributeMaxDynamicSharedMemorySize, GEMM_SMEM);
    cudaFuncSetAttribute(tcgemm<3,0>, cudaFuncAttributeMaxDynamicSharedMemorySize, GEMM_SMEM);
    cudaFuncSetAttribute(tcgemm<4,0>, cudaFuncAttributeMaxDynamicSharedMemorySize, GEMM_SMEM);
    cudaFuncSetAttribute(tcgemm256<0,1>, cudaFuncAttributeMaxDynamicSharedMemorySize, GEMM256_SMEM);
    cudaFuncSetAttribute(tcgemm256<2,1>, cudaFuncAttributeMaxDynamicSharedMemorySize, GEMM256_SMEM);

    WSegs ws;
    ws.W[0] = w_qkv;            ws.dst[0] = W_QKV;  ws.K[0] = 384;  ws.N[0] = 1152;
    ws.W[1] = w_knn;            ws.dst[1] = W_KNN1; ws.K[1] = 384;  ws.N[1] = 384;
    ws.W[2] = w_knn + 384*384;  ws.dst[2] = W_KNN2; ws.K[2] = 384;  ws.N[2] = 384;
    ws.W[3] = w_proj;           ws.dst[3] = W_PROJ; ws.K[3] = 384;  ws.N[3] = 384;
    ws.W[4] = w_g1;             ws.dst[4] = W_G1;   ws.K[4] = 768;  ws.N[4] = 384;
    ws.W[5] = w_g2;             ws.dst[5] = W_G2;   ws.K[5] = 384;  ws.N[5] = 384;
    ws.W[6] = w_fc1;            ws.dst[6] = W_FC1;  ws.K[6] = 384;  ws.N[6] = 1536;
    ws.W[7] = w_fc2;            ws.dst[7] = W_FC2;  ws.K[7] = 1536; ws.N[7] = 384;
    int tot = 0;
    for (int i = 0; i < 8; i++) {
        ws.t0[i] = tot;
        tot += (ws.K[i] / 32) * (ws.N[i] / 32);
    }
    wsplit_all<<<tot, 256>>>(ws, wh);

    ln_fp16_kernel<<<TOK, 128>>>(x, ln1_g, ln1_b, nx);
    detect_kernel<<<1, 32>>>((const unsigned int*)knnidx);

    // merged [qkv | P | R2] = nx @ [W_qkv | W1 | W2]  (N=1920, one launch)
    tcgemm256<0,1><<<dim3(15, 32), 256, GEMM256_SMEM>>>(nx, wh + W_QKV,
        nullptr, qkvpr, QS, 384, nullptr);
    // fp16 flash attention (2x64-query tiles per block, single wave)
    attn_mma_kernel<<<dim3(NSEQ / 128, NHEAD, 4), 128, ATTN_SMEM>>>(qkvpr, ap);
    // attn = attnP @ w_proj + b_proj -> fp32 attn + fp16 gi left half
    tcgemm<1,2><<<dim3(3, 64), 256, GEMM_SMEM>>>(ap, wh + W_PROJ,
        attn, gi, 384, 384, b_proj, nullptr, nullptr, nullptr);

    // EdgeConv gather from merged buffer
    knn_kernel<<<TOK, 384>>>(knnidx, qkvpr, b_knn, knn, gi);

    // gate path (gi assembled in place by proj + knn)
    tcgemm<2,1><<<dim3(3, 64), 256, GEMM_SMEM>>>(gi, wh + W_G1,
        nullptr, g1, 384, 768, b_g1, nullptr, nullptr, nullptr);
    tcgemm<3,0><<<dim3(3, 64), 256, GEMM_SMEM>>>(g1, wh + W_G2,
        x1, nullptr, 384, 384, b_g2, x, attn, knn);

    // FFN
    ln_fp16_kernel<<<TOK, 128>>>(x1, ln2_g, ln2_b, nx2);
    tcgemm256<2,1><<<dim3(12, 32), 256, GEMM256_SMEM>>>(nx2, wh + W_FC1,
        nullptr, hb, 1536, 384, b_fc1);
    tcgemm<4,0><<<dim3(3, 64), 256, GEMM_SMEM>>>(hb, wh + W_FC2,
        out, nullptr, 384, 1536, b_fc2, x1, nullptr, nullptr);

    (void)in_sizes; (void)n_in; (void)out_size;
}

// round 16
// speedup vs baseline: 1.0229x; 1.0229x over previous
#include <cuda_runtime.h>
#include <cuda_fp16.h>
#include <math.h>
#include <cstdint>

#define TOK   8192
#define DIM   384
#define NSEQ  2048
#define NHEAD 6
#define HD    64
#define KNN   8
#define QS    1920   // row stride of merged [q|k|v|P|R2] buffer
#define ATTN_BLOCKS 768

// ---------------- static scratch (no allocations allowed) -------------------
// fp32 floats: attn@0, knn@3145728, x1@6291456
__device__ __align__(128) float g_buf[9437184];
__device__ int g_idx64;

__device__ __align__(128) __half g_nx[TOK * DIM];
__device__ __align__(128) __half g_qkvpr[TOK * QS];   // [q|k|v|P|R2]
__device__ __align__(128) __half g_ap[TOK * DIM];
__device__ __align__(128) __half g_gi[TOK * 2 * DIM];
__device__ __align__(128) __half g_g1[TOK * DIM];
__device__ __align__(128) __half g_nx2[TOK * DIM];
__device__ __align__(128) __half g_hb[TOK * 4 * DIM];
__device__ __align__(128) __half g_wh[2506752];

#define W_QKV  0          // 1152x384
#define W_KNN1 442368     //  384x384
#define W_KNN2 589824     //  384x384
#define W_PROJ 737280     //  384x384
#define W_G1   884736     //  384x768
#define W_G2   1179648    //  384x384
#define W_FC1  1327104    // 1536x384
#define W_FC2  1916928    //  384x1536

// ---------------- helpers ----------------------------------------------------
__device__ __forceinline__ uint32_t smem_to_u32(const void* p) {
    uint32_t a;
    asm("{ .reg .u64 t; cvta.to.shared.u64 t, %1; cvt.u32.u64 %0, t; }" : "=r"(a) : "l"(p));
    return a;
}
#define STS128(r0, r1, r2, r3, sa) \
    asm volatile("st.shared.v4.b32 [%0], {%1, %2, %3, %4};" \
                 :: "r"(sa), "r"(r0), "r"(r1), "r"(r2), "r"(r3) : "memory")
#define SWZ128(o) ((o) ^ (((o) >> 3) & 0x70))
#define CP_ASYNC16(dst, src) \
    asm volatile("cp.async.cg.shared.global [%0], [%1], 16;" :: "r"(dst), "l"(src) : "memory")
#define CP_COMMIT() asm volatile("cp.async.commit_group;" ::: "memory")
#define CP_WAIT0()  asm volatile("cp.async.wait_group 0;" ::: "memory")
#define CP_WAIT1()  asm volatile("cp.async.wait_group 1;" ::: "memory")

__device__ __forceinline__ void ldsm4(uint32_t* r, uint32_t addr) {
    asm volatile("ldmatrix.sync.aligned.m8n8.x4.shared.b16 {%0,%1,%2,%3}, [%4];"
                 : "=r"(r[0]), "=r"(r[1]), "=r"(r[2]), "=r"(r[3]) : "r"(addr));
}
__device__ __forceinline__ void ldsm4t(uint32_t* r, uint32_t addr) {
    asm volatile("ldmatrix.sync.aligned.m8n8.x4.trans.shared.b16 {%0,%1,%2,%3}, [%4];"
                 : "=r"(r[0]), "=r"(r[1]), "=r"(r[2]), "=r"(r[3]) : "r"(addr));
}
__device__ __forceinline__ void mma16816(float* d, const uint32_t* a, const uint32_t* b) {
    asm volatile("mma.sync.aligned.m16n8k16.row.col.f32.f16.f16.f32 "
                 "{%0,%1,%2,%3}, {%4,%5,%6,%7}, {%8,%9}, {%0,%1,%2,%3};"
                 : "+f"(d[0]), "+f"(d[1]), "+f"(d[2]), "+f"(d[3])
                 : "r"(a[0]), "r"(a[1]), "r"(a[2]), "r"(a[3]), "r"(b[0]), "r"(b[1]));
}

__device__ __forceinline__ float geluf(float v) {
    return 0.5f * v * (1.0f + erff(v * 0.70710678118654752f));
}
__device__ __forceinline__ unsigned pk2h(float a, float b) {
    __half2 t = __floats2half2_rn(a, b);
    return *reinterpret_cast<unsigned*>(&t);
}

// ---------------- combined weight transpose -> fp16 (single launch) ---------
struct WSegs {
    const float* W[8];
    int dst[8];
    int K[8];
    int N[8];
    int t0[8];
};

__global__ void __launch_bounds__(256) wsplit_all(WSegs s, __half* __restrict__ ohb)
{
    __shared__ float t[32][33];
    int tb = blockIdx.x;
    int si = 0;
    #pragma unroll
    for (int i = 1; i < 8; i++) si = (tb >= s.t0[i]) ? i : si;
    int lt = tb - s.t0[si];
    const float* W = s.W[si];
    __half* oh = ohb + s.dst[si];
    int K = s.K[si], N = s.N[si];
    int ntx = N >> 5;
    int n0 = (lt % ntx) * 32, k0 = (lt / ntx) * 32;
    int tx = threadIdx.x & 31, ty = threadIdx.x >> 5;
    #pragma unroll
    for (int r = 0; r < 4; r++)
        t[ty + r * 8][tx] = W[(size_t)(k0 + ty + r * 8) * N + n0 + tx];
    __syncthreads();
    #pragma unroll
    for (int r = 0; r < 4; r++) {
        int n = n0 + ty + r * 8, k = k0 + tx;
        oh[(size_t)n * K + k] = __float2half_rn(t[tx][ty + r * 8]);
    }
}

// ---------------- LayerNorm -> fp16 ------------------------------------------
__global__ void __launch_bounds__(128) ln_fp16_kernel(const float* __restrict__ x,
    const float* __restrict__ g, const float* __restrict__ b,
    __half* __restrict__ oh)
{
    __shared__ float s1[4], s2[4];
    int row = blockIdx.x, t = threadIdx.x;
    const float* xr = x + (size_t)row * DIM;
    float v0 = xr[t], v1 = xr[t + 128], v2 = xr[t + 256];
    float sum = v0 + v1 + v2;
    float sq  = v0 * v0 + v1 * v1 + v2 * v2;
    #pragma unroll
    for (int o = 16; o > 0; o >>= 1) {
        sum += __shfl_xor_sync(0xffffffffu, sum, o);
        sq  += __shfl_xor_sync(0xffffffffu, sq,  o);
    }
    int w = t >> 5;
    if ((t & 31) == 0) { s1[w] = sum; s2[w] = sq; }
    __syncthreads();
    sum = s1[0] + s1[1] + s1[2] + s1[3];
    sq  = s2[0] + s2[1] + s2[2] + s2[3];
    float mu  = sum * (1.0f / DIM);
    float var = sq * (1.0f / DIM) - mu * mu;
    float rs  = rsqrtf(var + 1e-5f);
    size_t base = (size_t)row * DIM;
    #pragma unroll
    for (int it = 0; it < 3; it++) {
        int c = t + it * 128;
        float vv = (it == 0 ? v0 : it == 1 ? v1 : v2);
        float f = (vv - mu) * rs * g[c] + b[c];
        oh[base + c] = __float2half_rn(f);
    }
}

// ---------------- int32/int64 detection -------------------------------------
__global__ void detect_kernel(const unsigned int* __restrict__ w)
{
    if (threadIdx.x == 0) {
        unsigned int nz = 0;
        for (int i = 0; i < 512; i++) nz |= w[2 * i + 1];
        g_idx64 = (nz == 0) ? 1 : 0;
    }
}

// ---------------- fp16 GEMM 128x128, single-term, cp.async 2-stage ----------
#define GEMM_SMEM 65536
#define STAGE_SZ  32768u

template <int EPI, int OUTP>
__global__ void __launch_bounds__(256) tcgemm(
    const __half* __restrict__ A,
    const __half* __restrict__ B,
    float* __restrict__ C, __half* __restrict__ Ch,
    int N, int K,
    const float* __restrict__ bias, const float* __restrict__ e1,
    const float* __restrict__ e2, const float* __restrict__ e3)
{
    extern __shared__ char smem[];
    uint32_t sb = smem_to_u32(smem);
    int tid = threadIdx.x, warp = tid >> 5, lane = tid & 31;
    int wr = warp >> 2, wc = warp & 3;
    int n0 = blockIdx.x * 128, m0 = blockIdx.y * 128;

    float acc[4][4][4];
    #pragma unroll
    for (int i = 0; i < 4; i++)
        #pragma unroll
        for (int j = 0; j < 4; j++)
            #pragma unroll
            for (int q = 0; q < 4; q++) acc[i][j][q] = 0.f;

    const __half* src2[2] = { A + (size_t)m0 * K, B + (size_t)n0 * K };

    int lrow = tid >> 3, lseg = tid & 7;
    uint32_t lsw[4];
    #pragma unroll
    for (int i = 0; i < 4; i++)
        lsw[i] = SWZ128((uint32_t)((lrow + i * 32) * 128 + lseg * 16));

    int lr = lane & 7, ls = lane >> 3;
    int a_row = wr * 64 + (ls & 1) * 8 + lr;
    int a_kb  = (ls >> 1) * 16;
    int b_row = wc * 32 + (ls >> 1) * 8 + lr;
    int b_kb  = (ls & 1) * 16;

    int nch = K >> 6;

    #pragma unroll
    for (int t = 0; t < 2; t++) {
        const __half* base = src2[t];
        #pragma unroll
        for (int i = 0; i < 4; i++)
            CP_ASYNC16(sb + t * 16384u + lsw[i],
                       base + (size_t)(lrow + i * 32) * K + lseg * 8);
    }
    CP_COMMIT();

    for (int ch = 0; ch < nch; ch++) {
        if (ch + 1 < nch) {
            uint32_t st = ((ch + 1) & 1) * STAGE_SZ;
            int k0 = (ch + 1) << 6;
            #pragma unroll
            for (int t = 0; t < 2; t++) {
                const __half* base = src2[t] + k0;
                #pragma unroll
                for (int i = 0; i < 4; i++)
                    CP_ASYNC16(sb + st + t * 16384u + lsw[i],
                               base + (size_t)(lrow + i * 32) * K + lseg * 8);
            }
            CP_COMMIT();
            CP_WAIT1();
        } else {
            CP_WAIT0();
        }
        __syncthreads();

        uint32_t st = (ch & 1) * STAGE_SZ;
        #pragma unroll
        for (int ks = 0; ks < 4; ks++) {
            uint32_t ah[4][4], bh[4][2];
            #pragma unroll
            for (int mi = 0; mi < 4; mi++) {
                uint32_t off = (uint32_t)((a_row + mi * 16) * 128 + ks * 32 + a_kb);
                ldsm4(ah[mi], sb + st + SWZ128(off));
            }
            #pragma unroll
            for (int np = 0; np < 2; np++) {
                uint32_t off = (uint32_t)((b_row + np * 16) * 128 + ks * 32 + b_kb);
                uint32_t t4[4];
                ldsm4(t4, sb + st + 16384u + SWZ128(off));
                bh[np * 2][0] = t4[0]; bh[np * 2][1] = t4[1];
                bh[np * 2 + 1][0] = t4[2]; bh[np * 2 + 1][1] = t4[3];
            }
            #pragma unroll
            for (int mi = 0; mi < 4; mi++)
                #pragma unroll
                for (int nj = 0; nj < 4; nj++)
                    mma16816(acc[mi][nj], ah[mi], bh[nj]);
        }
        __syncthreads();
    }

    int g = lane >> 2, tg = lane & 3;
    #pragma unroll
    for (int mi = 0; mi < 4; mi++)
        #pragma unroll
        for (int nj = 0; nj < 4; nj++) {
            int col = n0 + wc * 32 + nj * 8 + 2 * tg;
            float bcol0 = 0.f, bcol1 = 0.f;
            if (EPI >= 1) { bcol0 = bias[col]; bcol1 = bias[col + 1]; }
            #pragma unroll
            for (int half = 0; half < 2; half++) {
                size_t row = (size_t)(m0 + wr * 64 + mi * 16 + g + half * 8);
                float v0 = acc[mi][nj][half * 2]     + bcol0;
                float v1 = acc[mi][nj][half * 2 + 1] + bcol1;
                if (EPI == 2) { v0 = geluf(v0); v1 = geluf(v1); }
                if (EPI == 3) {
                    size_t off = row * (size_t)N + (size_t)col;
                    float2 a1 = *(const float2*)(e1 + off);
                    float2 a2 = *(const float2*)(e2 + off);
                    float2 a3 = *(const float2*)(e3 + off);
                    float s0 = 1.0f / (1.0f + expf(-v0));
                    float s1 = 1.0f / (1.0f + expf(-v1));
                    v0 = a1.x + (1.0f - s0) * a2.x + s0 * a3.x;
                    v1 = a1.y + (1.0f - s1) * a2.y + s1 * a3.y;
                }
                if (EPI == 4) {
                    float2 a1 = *(const float2*)(e1 + row * (size_t)N + col);
                    v0 += a1.x; v1 += a1.y;
                }
                if (OUTP == 0) {
                    *(float2*)(C + row * (size_t)N + col) = make_float2(v0, v1);
                } else if (OUTP == 1) {
                    *(unsigned*)(Ch + row * (size_t)N + col) = pk2h(v0, v1);
                } else {
                    *(float2*)(C + row * (size_t)N + col) = make_float2(v0, v1);
                    *(unsigned*)(Ch + row * 768 + col) = pk2h(v0, v1);
                }
            }
        }
}

// ---------------- fp16 GEMM 256x128, warp tile 64x64, cp.async 2-stage ------
#define GEMM256_SMEM 98304
#define STG256 49152u

template <int EPI, int OUTP>
__global__ void __launch_bounds__(256) tcgemm256(
    const __half* __restrict__ A,
    const __half* __restrict__ B,
    float* __restrict__ C, __half* __restrict__ Ch,
    int N, int K,
    const float* __restrict__ bias)
{
    extern __shared__ char smem[];
    uint32_t sb = smem_to_u32(smem);
    int tid = threadIdx.x, warp = tid >> 5, lane = tid & 31;
    int wr = warp >> 1, wc = warp & 1;
    int n0 = blockIdx.x * 128, m0 = blockIdx.y * 256;

    float acc[4][8][4];
    #pragma unroll
    for (int i = 0; i < 4; i++)
        #pragma unroll
        for (int j = 0; j < 8; j++)
            #pragma unroll
            for (int q = 0; q < 4; q++) acc[i][j][q] = 0.f;

    const __half* pA = A + (size_t)m0 * K;
    const __half* pB = B + (size_t)n0 * K;

    int lrow = tid >> 3, lseg = tid & 7;
    uint32_t lsw[8];
    #pragma unroll
    for (int i = 0; i < 8; i++)
        lsw[i] = SWZ128((uint32_t)((lrow + i * 32) * 128 + lseg * 16));

    int lr = lane & 7, ls = lane >> 3;
    int a_row = wr * 64 + (ls & 1) * 8 + lr;
    int a_kb  = (ls >> 1) * 16;
    int b_row = wc * 64 + (ls >> 1) * 8 + lr;
    int b_kb  = (ls & 1) * 16;

    int nch = K >> 6;

    #pragma unroll
    for (int i = 0; i < 8; i++)
        CP_ASYNC16(sb + lsw[i], pA + (size_t)(lrow + i * 32) * K + lseg * 8);
    #pragma unroll
    for (int i = 0; i < 4; i++)
        CP_ASYNC16(sb + 32768u + lsw[i], pB + (size_t)(lrow + i * 32) * K + lseg * 8);
    CP_COMMIT();

    for (int ch = 0; ch < nch; ch++) {
        if (ch + 1 < nch) {
            uint32_t st = ((ch + 1) & 1) * STG256;
            int k0 = (ch + 1) << 6;
            #pragma unroll
            for (int i = 0; i < 8; i++)
                CP_ASYNC16(sb + st + lsw[i], pA + k0 + (size_t)(lrow + i * 32) * K + lseg * 8);
            #pragma unroll
            for (int i = 0; i < 4; i++)
                CP_ASYNC16(sb + st + 32768u + lsw[i], pB + k0 + (size_t)(lrow + i * 32) * K + lseg * 8);
            CP_COMMIT();
            CP_WAIT1();
        } else {
            CP_WAIT0();
        }
        __syncthreads();

        uint32_t st = (ch & 1) * STG256;
        #pragma unroll
        for (int ks = 0; ks < 4; ks++) {
            uint32_t ah[4][4], bh[8][2];
            #pragma unroll
            for (int mi = 0; mi < 4; mi++) {
                uint32_t off = (uint32_t)((a_row + mi * 16) * 128 + ks * 32 + a_kb);
                ldsm4(ah[mi], sb + st + SWZ128(off));
            }
            #pragma unroll
            for (int np = 0; np < 4; np++) {
                uint32_t off = (uint32_t)((b_row + np * 16) * 128 + ks * 32 + b_kb);
                uint32_t t4[4];
                ldsm4(t4, sb + st + 32768u + SWZ128(off));
                bh[np * 2][0] = t4[0]; bh[np * 2][1] = t4[1];
                bh[np * 2 + 1][0] = t4[2]; bh[np * 2 + 1][1] = t4[3];
            }
            #pragma unroll
            for (int mi = 0; mi < 4; mi++)
                #pragma unroll
                for (int nj = 0; nj < 8; nj++)
                    mma16816(acc[mi][nj], ah[mi], bh[nj]);
        }
        __syncthreads();
    }

    int g = lane >> 2, tg = lane & 3;
    #pragma unroll
    for (int mi = 0; mi < 4; mi++)
        #pragma unroll
        for (int nj = 0; nj < 8; nj++) {
            int col = n0 + wc * 64 + nj * 8 + 2 * tg;
            float bcol0 = 0.f, bcol1 = 0.f;
            if (EPI >= 1) { bcol0 = bias[col]; bcol1 = bias[col + 1]; }
            #pragma unroll
            for (int half = 0; half < 2; half++) {
                size_t row = (size_t)(m0 + wr * 64 + mi * 16 + g + half * 8);
                float v0 = acc[mi][nj][half * 2]     + bcol0;
                float v1 = acc[mi][nj][half * 2 + 1] + bcol1;
                if (EPI == 2) { v0 = geluf(v0); v1 = geluf(v1); }
                if (OUTP == 0) {
                    *(float2*)(C + row * (size_t)N + col) = make_float2(v0, v1);
                } else {
                    *(unsigned*)(Ch + row * (size_t)N + col) = pk2h(v0, v1);
                }
            }
        }
}

// ---------------- fused: flash attention (blocks 0..767) + EdgeConv gather --
// attention: 64-query blocks, cp.async 2-stage; smem 40KB, 128 threads, occ 3
#define ATTN_SMEM 40960

__global__ void __launch_bounds__(128, 3) attn_knn_kernel(
    const __half* __restrict__ qkv,
    __half* __restrict__ oph,
    const void* __restrict__ idxraw, const float* __restrict__ bknn,
    float* __restrict__ knnout, __half* __restrict__ gih)
{
    if (blockIdx.x >= ATTN_BLOCKS) {
        // ---- EdgeConv gather for one token ----
        int mtok = blockIdx.x - ATTN_BLOCKS;
        int tid = threadIdx.x;
        int b = mtok >> 11;
        int n = mtok & 2047;
        int is64 = g_idx64;
        const long long* i64 = (const long long*)idxraw;
        const int* i32 = (const int*)idxraw;
        size_t ib = (size_t)b * KNN * NSEQ + n;
        long long ids[KNN];
        #pragma unroll
        for (int k = 0; k < KNN; k++)
            ids[k] = is64 ? i64[ib + (size_t)k * NSEQ]
                          : (long long)i32[ib + (size_t)k * NSEQ];
        #pragma unroll
        for (int it = 0; it < 3; it++) {
            int c = tid + it * 128;
            size_t moff = (size_t)mtok * QS + 1152 + c;
            float base = __half2float(qkv[moff + 384]) - __half2float(qkv[moff]) + bknn[c];
            float best = -3.4e38f;
            #pragma unroll
            for (int k = 0; k < KNN; k++) {
                float v = __half2float(qkv[(size_t)ids[k] * QS + 1152 + c]) + base;
                v = v > 0.f ? v : 0.2f * v;
                best = fmaxf(best, v);
            }
            knnout[(size_t)mtok * DIM + c] = best;
            gih[(size_t)mtok * 768 + 384 + c] = __float2half_rn(best);
        }
        return;
    }

    // ---- attention ----
    extern __shared__ char smc[];
    uint32_t sb = smem_to_u32(smc);
    int bx = blockIdx.x;
    int qt = bx & 31;
    int h  = (bx >> 5) % NHEAD;
    int b  = bx / (32 * NHEAD);
    int tid = threadIdx.x, warp = tid >> 5, lane = tid & 31;
    int lr = lane & 7, ls = lane >> 3;
    int g = lane >> 2, tg = lane & 3;

    const int qbase = b * NSEQ + qt * 64;
    const int qcol = h * HD, kcol = DIM + h * HD, vcol = 2 * DIM + h * HD;

    int lrow = tid >> 3, lseg = tid & 7;
    uint32_t lsw[4];
    #pragma unroll
    for (int i = 0; i < 4; i++)
        lsw[i] = SWZ128((uint32_t)((lrow + i * 16) * 128 + lseg * 16));

    {
        int tokb = b * NSEQ;
        #pragma unroll
        for (int t = 0; t < 2; t++) {
            int colb = (t == 0) ? kcol : vcol;
            #pragma unroll
            for (int i = 0; i < 4; i++)
                CP_ASYNC16(sb + t * 8192u + lsw[i],
                           qkv + (size_t)(tokb + lrow + i * 16) * QS + colb + lseg * 8);
        }
        CP_COMMIT();
    }

    #pragma unroll
    for (int i = 0; i < 4; i++) {
        uint4 v = *reinterpret_cast<const uint4*>(
            qkv + (size_t)(qbase + lrow + i * 16) * QS + qcol + lseg * 8);
        STS128(v.x, v.y, v.z, v.w, sb + 32768u + lsw[i]);
    }
    __syncthreads();

    uint32_t Qf[4][4];
    {
        int a_row = warp * 16 + (ls & 1) * 8 + lr;
        int a_kb  = (ls >> 1) * 16;
        #pragma unroll
        for (int ks = 0; ks < 4; ks++) {
            uint32_t off = (uint32_t)(a_row * 128 + ks * 32 + a_kb);
            ldsm4(Qf[ks], sb + 32768u + SWZ128(off));
        }
    }
    __syncthreads();

    float O[8][4];
    #pragma unroll
    for (int t = 0; t < 8; t++)
        #pragma unroll
        for (int q = 0; q < 4; q++) O[t][q] = 0.f;
    float mrow[2] = {-1e30f, -1e30f}, lrowv[2] = {0.f, 0.f};

    const float SC = 0.125f * 1.44269504088896f;

    int kb_row = (ls >> 1) * 8 + lr;
    int kb_col = (ls & 1) * 16;
    int v_row = lane & 15;
    int v_col = (lane >> 4) * 16;

    for (int kt = 0; kt < NSEQ / 64; kt++) {
        if (kt + 1 < NSEQ / 64) {
            uint32_t st = ((kt + 1) & 1) * 16384u;
            int tokb = b * NSEQ + (kt + 1) * 64;
            #pragma unroll
            for (int t = 0; t < 2; t++) {
                int colb = (t == 0) ? kcol : vcol;
                #pragma unroll
                for (int i = 0; i < 4; i++)
                    CP_ASYNC16(sb + st + t * 8192u + lsw[i],
                               qkv + (size_t)(tokb + lrow + i * 16) * QS + colb + lseg * 8);
            }
            CP_COMMIT();
            CP_WAIT1();
        } else {
            CP_WAIT0();
        }
        __syncthreads();

        uint32_t st = (kt & 1) * 16384u;

        float sacc[8][4];
        #pragma unroll
        for (int t = 0; t < 8; t++)
            #pragma unroll
            for (int q = 0; q < 4; q++) sacc[t][q] = 0.f;
        #pragma unroll
        for (int ks = 0; ks < 4; ks++) {
            #pragma unroll
            for (int np = 0; np < 4; np++) {
                uint32_t off = (uint32_t)((np * 16 + kb_row) * 128 + ks * 32 + kb_col);
                uint32_t th[4];
                ldsm4(th, sb + st + SWZ128(off));
                mma16816(sacc[np * 2],     Qf[ks], th);
                mma16816(sacc[np * 2 + 1], Qf[ks], th + 2);
            }
        }

        float rmax[2] = {-1e30f, -1e30f};
        #pragma unroll
        for (int t = 0; t < 8; t++) {
            #pragma unroll
            for (int q = 0; q < 4; q++) sacc[t][q] *= SC;
            rmax[0] = fmaxf(rmax[0], fmaxf(sacc[t][0], sacc[t][1]));
            rmax[1] = fmaxf(rmax[1], fmaxf(sacc[t][2], sacc[t][3]));
        }
        #pragma unroll
        for (int o = 1; o <= 2; o <<= 1) {
            rmax[0] = fmaxf(rmax[0], __shfl_xor_sync(0xffffffffu, rmax[0], o));
            rmax[1] = fmaxf(rmax[1], __shfl_xor_sync(0xffffffffu, rmax[1], o));
        }
        float mn0 = fmaxf(mrow[0], rmax[0]), mn1 = fmaxf(mrow[1], rmax[1]);
        if (mn0 != mrow[0] || mn1 != mrow[1]) {
            float corr0 = exp2f(mrow[0] - mn0), corr1 = exp2f(mrow[1] - mn1);
            lrowv[0] *= corr0;
            lrowv[1] *= corr1;
            #pragma unroll
            for (int t = 0; t < 8; t++) {
                O[t][0] *= corr0; O[t][1] *= corr0;
                O[t][2] *= corr1; O[t][3] *= corr1;
            }
            mrow[0] = mn0; mrow[1] = mn1;
        }
        float rsum[2] = {0.f, 0.f};
        #pragma unroll
        for (int t = 0; t < 8; t++) {
            sacc[t][0] = exp2f(sacc[t][0] - mn0);
            sacc[t][1] = exp2f(sacc[t][1] - mn0);
            sacc[t][2] = exp2f(sacc[t][2] - mn1);
            sacc[t][3] = exp2f(sacc[t][3] - mn1);
            rsum[0] += sacc[t][0] + sacc[t][1];
            rsum[1] += sacc[t][2] + sacc[t][3];
        }
        #pragma unroll
        for (int o = 1; o <= 2; o <<= 1) {
            rsum[0] += __shfl_xor_sync(0xffffffffu, rsum[0], o);
            rsum[1] += __shfl_xor_sync(0xffffffffu, rsum[1], o);
        }
        lrowv[0] += rsum[0];
        lrowv[1] += rsum[1];

        uint32_t ph[4][4];
        #pragma unroll
        for (int j = 0; j < 4; j++) {
            ph[j][0] = pk2h(sacc[2 * j][0],     sacc[2 * j][1]);
            ph[j][1] = pk2h(sacc[2 * j][2],     sacc[2 * j][3]);
            ph[j][2] = pk2h(sacc[2 * j + 1][0], sacc[2 * j + 1][1]);
            ph[j][3] = pk2h(sacc[2 * j + 1][2], sacc[2 * j + 1][3]);
        }

        #pragma unroll
        for (int ks = 0; ks < 4; ks++) {
            #pragma unroll
            for (int np = 0; np < 4; np++) {
                uint32_t off = (uint32_t)((ks * 16 + v_row) * 128 + np * 32 + v_col);
                uint32_t vh[4];
                ldsm4t(vh, sb + st + 8192u + SWZ128(off));
                mma16816(O[np * 2],     ph[ks], vh);
                mma16816(O[np * 2 + 1], ph[ks], vh + 2);
            }
        }
        __syncthreads();
    }

    float inv0 = 1.0f / lrowv[0], inv1 = 1.0f / lrowv[1];
    size_t row0 = (size_t)(qbase + warp * 16 + g);
    #pragma unroll
    for (int t = 0; t < 8; t++) {
        int col = h * HD + t * 8 + tg * 2;
        *(unsigned*)(oph + row0 * DIM + col)       = pk2h(O[t][0] * inv0, O[t][1] * inv0);
        *(unsigned*)(oph + (row0 + 8) * DIM + col) = pk2h(O[t][2] * inv1, O[t][3] * inv1);
    }
}

// ---------------- launch ----------------------------------------------------
extern "C" void kernel_launch(void* const* d_in, const int* in_sizes, int n_in,
                              void* d_out, int out_size)
{
    const float* x      = (const float*)d_in[0];
    const void*  knnidx = d_in[1];
    const float* ln1_g  = (const float*)d_in[2];
    const float* ln1_b  = (const float*)d_in[3];
    const float* w_qkv  = (const float*)d_in[4];
    const float* w_proj = (const float*)d_in[5];
    const float* b_proj = (const float*)d_in[6];
    const float* w_knn  = (const float*)d_in[7];
    const float* b_knn  = (const float*)d_in[8];
    const float* w_g1   = (const float*)d_in[9];
    const float* b_g1   = (const float*)d_in[10];
    const float* w_g2   = (const float*)d_in[11];
    const float* b_g2   = (const float*)d_in[12];
    const float* ln2_g  = (const float*)d_in[13];
    const float* ln2_b  = (const float*)d_in[14];
    const float* w_fc1  = (const float*)d_in[15];
    const float* b_fc1  = (const float*)d_in[16];
    const float* w_fc2  = (const float*)d_in[17];
    const float* b_fc2  = (const float*)d_in[18];
    float* out = (float*)d_out;

    float* buf = nullptr;
    cudaGetSymbolAddress((void**)&buf, g_buf);
    float* attn = buf + 0;
    float* knn  = buf + 3145728;
    float* x1   = buf + 6291456;

    __half *nx, *qkvpr, *ap, *gi, *g1, *nx2, *hb, *wh;
    cudaGetSymbolAddress((void**)&nx,    g_nx);
    cudaGetSymbolAddress((void**)&qkvpr, g_qkvpr);
    cudaGetSymbolAddress((void**)&ap,    g_ap);
    cudaGetSymbolAddress((void**)&gi,    g_gi);
    cudaGetSymbolAddress((void**)&g1,    g_g1);
    cudaGetSymbolAddress((void**)&nx2,   g_nx2);
    cudaGetSymbolAddress((void**)&hb,    g_hb);
    cudaGetSymbolAddress((void**)&wh,    g_wh);

    cudaFuncSetAttribute(attn_knn_kernel, cudaFuncAttributeMaxDynamicSharedMemorySize, ATTN_SMEM);
    cudaFuncSetAttribute(tcgemm<1,2>, cudaFuncAttributeMaxDynamicSharedMemorySize, GEMM_SMEM);
    cudaFuncSetAttribute(tcgemm<2,1>, cudaFuncAttributeMaxDynamicSharedMemorySize, GEMM_SMEM);
    cudaFuncSetAttribute(tcgemm<3,0>, cudaFuncAttributeMaxDynamicSharedMemorySize, GEMM_SMEM);
    cudaFuncSetAttribute(tcgemm<4,0>, cudaFuncAttributeMaxDynamicSharedMemorySize, GEMM_SMEM);
    cudaFuncSetAttribute(tcgemm256<0,1>, cudaFuncAttributeMaxDynamicSharedMemorySize, GEMM256_SMEM);
    cudaFuncSetAttribute(tcgemm256<2,1>, cudaFuncAttributeMaxDynamicSharedMemorySize, GEMM256_SMEM);

    WSegs ws;
    ws.W[0] = w_qkv;            ws.dst[0] = W_QKV;  ws.K[0] = 384;  ws.N[0] = 1152;
    ws.W[1] = w_knn;            ws.dst[1] = W_KNN1; ws.K[1] = 384;  ws.N[1] = 384;
    ws.W[2] = w_knn + 384*384;  ws.dst[2] = W_KNN2; ws.K[2] = 384;  ws.N[2] = 384;
    ws.W[3] = w_proj;           ws.dst[3] = W_PROJ; ws.K[3] = 384;  ws.N[3] = 384;
    ws.W[4] = w_g1;             ws.dst[4] = W_G1;   ws.K[4] = 768;  ws.N[4] = 384;
    ws.W[5] = w_g2;             ws.dst[5] = W_G2;   ws.K[5] = 384;  ws.N[5] = 384;
    ws.W[6] = w_fc1;            ws.dst[6] = W_FC1;  ws.K[6] = 384;  ws.N[6] = 1536;
    ws.W[7] = w_fc2;            ws.dst[7] = W_FC2;  ws.K[7] = 1536; ws.N[7] = 384;
    int tot = 0;
    for (int i = 0; i < 8; i++) {
        ws.t0[i] = tot;
        tot += (ws.K[i] / 32) * (ws.N[i] / 32);
    }
    wsplit_all<<<tot, 256>>>(ws, wh);

    ln_fp16_kernel<<<TOK, 128>>>(x, ln1_g, ln1_b, nx);
    detect_kernel<<<1, 32>>>((const unsigned int*)knnidx);

    // merged [qkv | P | R2] = nx @ [W_qkv | W1 | W2]  (N=1920, one launch)
    tcgemm256<0,1><<<dim3(15, 32), 256, GEMM256_SMEM>>>(nx, wh + W_QKV,
        nullptr, qkvpr, QS, 384, nullptr);
    // fused: flash attention (blocks 0..767) + EdgeConv gather (768..8959)
    attn_knn_kernel<<<ATTN_BLOCKS + TOK, 128, ATTN_SMEM>>>(qkvpr, ap,
        knnidx, b_knn, knn, gi);
    // attn = attnP @ w_proj + b_proj -> fp32 attn + fp16 gi left half
    tcgemm<1,2><<<dim3(3, 64), 256, GEMM_SMEM>>>(ap, wh + W_PROJ,
        attn, gi, 384, 384, b_proj, nullptr, nullptr, nullptr);

    // gate path (gi assembled in place by proj + fused knn)
    tcgemm<2,1><<<dim3(3, 64), 256, GEMM_SMEM>>>(gi, wh + W_G1,
        nullptr, g1, 384, 768, b_g1, nullptr, nullptr, nullptr);
    tcgemm<3,0><<<dim3(3, 64), 256, GEMM_SMEM>>>(g1, wh + W_G2,
        x1, nullptr, 384, 384, b_g2, x, attn, knn);

    // FFN
    ln_fp16_kernel<<<TOK, 128>>>(x1, ln2_g, ln2_b, nx2);
    tcgemm256<2,1><<<dim3(12, 32), 256, GEMM256_SMEM>>>(nx2, wh + W_FC1,
        nullptr, hb, 1536, 384, b_fc1);
    tcgemm<4,0><<<dim3(3, 64), 256, GEMM_SMEM>>>(hb, wh + W_FC2,
        out, nullptr, 384, 1536, b_fc2, x1, nullptr, nullptr);

    (void)in_sizes; (void)n_in; (void)out_size;
}